// round 1
// baseline (speedup 1.0000x reference)
#include <cuda_runtime.h>
#include <cstdint>

#define NN 50000
#define NE 800000
#define SCAN_B 1024
#define SCAN_NB ((NN + SCAN_B - 1) / SCAN_B)

// ---------------- scratch (static device allocations; no cudaMalloc) ----------------
__device__ int   g_cnt[NN];
__device__ int   g_rowptr[NN + 1];
__device__ int   g_fill[NN];
__device__ int   g_colsrc[NE];
__device__ float g_dinv[NN];
__device__ __align__(16) float g_bufA[(size_t)NN * 128];
__device__ __align__(16) float g_bufB[(size_t)NN * 128];
__device__ int   g_bsum[64];

// ---------------- degree / CSR build ----------------
__global__ void k_zero_cnt() {
    int i = blockIdx.x * blockDim.x + threadIdx.x;
    if (i < NN) g_cnt[i] = 0;
}

__global__ void k_count(const int* __restrict__ ei) {
    int e = blockIdx.x * blockDim.x + threadIdx.x;
    if (e < NE) atomicAdd(&g_cnt[ei[NE + e]], 1);
}

__global__ void k_dinv() {
    int i = blockIdx.x * blockDim.x + threadIdx.x;
    if (i < NN) g_dinv[i] = rsqrtf((float)(g_cnt[i] + 1));
}

__global__ void k_scan1() {
    __shared__ int s[SCAN_B];
    int t = threadIdx.x;
    int i = blockIdx.x * SCAN_B + t;
    int v = (i < NN) ? g_cnt[i] : 0;
    s[t] = v;
    __syncthreads();
    #pragma unroll
    for (int off = 1; off < SCAN_B; off <<= 1) {
        int add = (t >= off) ? s[t - off] : 0;
        __syncthreads();
        s[t] += add;
        __syncthreads();
    }
    if (i < NN) g_rowptr[i] = s[t] - v;  // exclusive within block
    if (t == SCAN_B - 1) g_bsum[blockIdx.x] = s[t];
}

__global__ void k_scan2() {
    // single thread: 49 block sums
    int run = 0;
    for (int b = 0; b < SCAN_NB; b++) {
        int v = g_bsum[b];
        g_bsum[b] = run;
        run += v;
    }
    g_rowptr[NN] = run;  // == NE
}

__global__ void k_scan3() {
    int i = blockIdx.x * SCAN_B + threadIdx.x;
    if (i < NN) {
        int r = g_rowptr[i] + g_bsum[blockIdx.x];
        g_rowptr[i] = r;
        g_fill[i] = r;
    }
}

__global__ void k_scatter(const int* __restrict__ ei) {
    int e = blockIdx.x * blockDim.x + threadIdx.x;
    if (e < NE) {
        int s = ei[e];
        int d = ei[NE + e];
        int pos = atomicAdd(&g_fill[d], 1);
        g_colsrc[pos] = s;
    }
}

// ---------------- GEMM with dinv[row] epilogue: U = (A @ W) * dinv[row] ----------------
// BM=64, BN=64, BK=16, 256 threads, 4x4 per thread.
// ASEL: 0 = external ptr, 1 = g_bufA, 2 = g_bufB.  OSEL: 1 = g_bufA, 2 = g_bufB.
template <int FIN, int FOUT, int ASEL, int OSEL>
__global__ void k_gemm_scale(const float* __restrict__ Aext,
                             const float* __restrict__ W) {
    const float* A = (ASEL == 0) ? Aext : ((ASEL == 1) ? g_bufA : g_bufB);
    float* U = (OSEL == 1) ? g_bufA : g_bufB;

    __shared__ float As[64][17];
    __shared__ float Ws[16][68];

    int tid = threadIdx.x;
    int row0 = blockIdx.x * 64;
    int col0 = blockIdx.y * 64;

    int lr = tid >> 2, lq = tid & 3;    // A tile load: row lr (0..63), float4 chunk lq (0..3)
    int wk = tid >> 4, wq = tid & 15;   // W tile load: k wk (0..15), float4 chunk wq (0..15)
    int ty = tid >> 4, tx = tid & 15;   // compute: rows ty*4.., cols tx*4..

    float acc[4][4] = {};

    for (int k0 = 0; k0 < FIN; k0 += 16) {
        float4 av = make_float4(0.f, 0.f, 0.f, 0.f);
        int ar = row0 + lr;
        if (ar < NN)
            av = *(const float4*)(A + (size_t)ar * FIN + k0 + lq * 4);
        As[lr][lq * 4 + 0] = av.x;
        As[lr][lq * 4 + 1] = av.y;
        As[lr][lq * 4 + 2] = av.z;
        As[lr][lq * 4 + 3] = av.w;

        float4 wv = *(const float4*)(W + (size_t)(k0 + wk) * FOUT + col0 + wq * 4);
        Ws[wk][wq * 4 + 0] = wv.x;
        Ws[wk][wq * 4 + 1] = wv.y;
        Ws[wk][wq * 4 + 2] = wv.z;
        Ws[wk][wq * 4 + 3] = wv.w;

        __syncthreads();
        #pragma unroll
        for (int k = 0; k < 16; k++) {
            float a[4], b[4];
            #pragma unroll
            for (int i = 0; i < 4; i++) a[i] = As[ty * 4 + i][k];
            #pragma unroll
            for (int j = 0; j < 4; j++) b[j] = Ws[k][tx * 4 + j];
            #pragma unroll
            for (int i = 0; i < 4; i++)
                #pragma unroll
                for (int j = 0; j < 4; j++)
                    acc[i][j] = fmaf(a[i], b[j], acc[i][j]);
        }
        __syncthreads();
    }

    #pragma unroll
    for (int i = 0; i < 4; i++) {
        int r = row0 + ty * 4 + i;
        if (r < NN) {
            float dd = g_dinv[r];
            float4 o;
            o.x = acc[i][0] * dd;
            o.y = acc[i][1] * dd;
            o.z = acc[i][2] * dd;
            o.w = acc[i][3] * dd;
            *(float4*)(U + (size_t)r * FOUT + col0 + tx * 4) = o;
        }
    }
}

// ---------------- CSR gather aggregation: H[d] = relu(dinv[d]*(sum_in U[s] + U[d]) + b) ----------------
template <int ISEL, int OSEL>
__global__ void k_agg128(const float* __restrict__ bias) {
    const float* U = (ISEL == 1) ? g_bufA : g_bufB;
    float* H = (OSEL == 1) ? g_bufA : g_bufB;
    int w = (blockIdx.x * blockDim.x + threadIdx.x) >> 5;
    int lane = threadIdx.x & 31;
    if (w >= NN) return;
    const float4* Uv = (const float4*)U;  // row stride = 32 float4
    float4 acc = Uv[(size_t)w * 32 + lane];  // self loop
    int e0 = g_rowptr[w], e1 = g_rowptr[w + 1];
    for (int e = e0; e < e1; e++) {
        int s = g_colsrc[e];
        float4 v = Uv[(size_t)s * 32 + lane];
        acc.x += v.x; acc.y += v.y; acc.z += v.z; acc.w += v.w;
    }
    float dd = g_dinv[w];
    float4 bb = ((const float4*)bias)[lane];
    float4 o;
    o.x = fmaxf(fmaf(acc.x, dd, bb.x), 0.f);
    o.y = fmaxf(fmaf(acc.y, dd, bb.y), 0.f);
    o.z = fmaxf(fmaf(acc.z, dd, bb.z), 0.f);
    o.w = fmaxf(fmaf(acc.w, dd, bb.w), 0.f);
    ((float4*)H)[(size_t)w * 32 + lane] = o;
}

template <int ISEL, int OSEL>
__global__ void k_agg64(const float* __restrict__ bias) {
    const float* U = (ISEL == 1) ? g_bufA : g_bufB;
    float* H = (OSEL == 1) ? g_bufA : g_bufB;
    int w = (blockIdx.x * blockDim.x + threadIdx.x) >> 5;
    int lane = threadIdx.x & 31;
    if (w >= NN) return;
    const float2* Uv = (const float2*)U;  // row stride = 32 float2
    float2 acc = Uv[(size_t)w * 32 + lane];
    int e0 = g_rowptr[w], e1 = g_rowptr[w + 1];
    for (int e = e0; e < e1; e++) {
        int s = g_colsrc[e];
        float2 v = Uv[(size_t)s * 32 + lane];
        acc.x += v.x; acc.y += v.y;
    }
    float dd = g_dinv[w];
    float2 bb = ((const float2*)bias)[lane];
    float2 o;
    o.x = fmaxf(fmaf(acc.x, dd, bb.x), 0.f);
    o.y = fmaxf(fmaf(acc.y, dd, bb.y), 0.f);
    ((float2*)H)[(size_t)w * 32 + lane] = o;
}

// ---------------- prototype-distance head + MLP + y copy ----------------
__device__ __forceinline__ float gelu_exact(float x) {
    return 0.5f * x * (1.0f + erff(x * 0.70710678118654752f));
}

__global__ void k_head(const float* __restrict__ prot,
                       const float* __restrict__ Wf0, const float* __restrict__ bf0,
                       const float* __restrict__ Wf1, const float* __restrict__ bf1,
                       const int* __restrict__ y,
                       float* __restrict__ out, int out_size) {
    __shared__ float hs[128][65];
    __shared__ float ps[16][64];
    __shared__ float pn[16];
    __shared__ float w0[16][8];
    __shared__ float b0[8];
    __shared__ float w1[8];
    __shared__ float b1s;

    const float* H = g_bufB;  // h3 lives in bufB
    int t = threadIdx.x;
    int nd0 = blockIdx.x * 128;

    for (int idx = t; idx < 128 * 64; idx += 128) {
        int r = idx >> 6, c = idx & 63;
        int node = nd0 + r;
        hs[r][c] = (node < NN) ? H[(size_t)node * 64 + c] : 0.f;
    }
    for (int idx = t; idx < 16 * 64; idx += 128)
        ps[idx >> 6][idx & 63] = prot[idx];
    if (t < 16 * 8) w0[t >> 3][t & 7] = Wf0[t];
    if (t < 8) { b0[t] = bf0[t]; w1[t] = Wf1[t]; }
    if (t == 0) b1s = bf1[0];
    __syncthreads();
    if (t < 16) {
        float s = 0.f;
        #pragma unroll
        for (int c = 0; c < 64; c++) s += ps[t][c] * ps[t][c];
        pn[t] = s;
    }
    __syncthreads();

    int node = nd0 + t;
    if (node < NN) {
        float hh = 0.f;
        #pragma unroll
        for (int c = 0; c < 64; c++) hh = fmaf(hs[t][c], hs[t][c], hh);

        float sim[16];
        #pragma unroll
        for (int k = 0; k < 16; k++) {
            float dot = 0.f;
            #pragma unroll
            for (int c = 0; c < 64; c++) dot = fmaf(hs[t][c], ps[k][c], dot);
            float d2 = fmaxf(hh + pn[k] - 2.0f * dot, 0.f);
            sim[k] = logf((d2 + 1.0f) / (d2 + 1e-4f));
        }

        float o = b1s;
        #pragma unroll
        for (int j = 0; j < 8; j++) {
            float z = b0[j];
            #pragma unroll
            for (int k = 0; k < 16; k++) z = fmaf(sim[k], w0[k][j], z);
            o = fmaf(gelu_exact(z), w1[j], o);
        }
        out[node] = 1.0f / (1.0f + expf(-o));
        if (NN + node < out_size) out[NN + node] = (float)y[node];
    }
}

// ---------------- launch ----------------
extern "C" void kernel_launch(void* const* d_in, const int* in_sizes, int n_in,
                              void* d_out, int out_size) {
    const float* x    = (const float*)d_in[0];
    const int*   ei   = (const int*)d_in[1];     // [2, NE] int32
    const int*   y    = (const int*)d_in[2];
    const float* W1   = (const float*)d_in[3];
    const float* b1   = (const float*)d_in[4];
    const float* W2   = (const float*)d_in[5];
    const float* b2   = (const float*)d_in[6];
    const float* W3   = (const float*)d_in[7];
    const float* b3   = (const float*)d_in[8];
    const float* prot = (const float*)d_in[9];
    const float* Wf0  = (const float*)d_in[10];
    const float* bf0  = (const float*)d_in[11];
    const float* Wf1  = (const float*)d_in[12];
    const float* bf1  = (const float*)d_in[13];
    float* out = (float*)d_out;

    // degree + CSR
    k_zero_cnt<<<(NN + 255) / 256, 256>>>();
    k_count<<<(NE + 255) / 256, 256>>>(ei);
    k_dinv<<<(NN + 255) / 256, 256>>>();
    k_scan1<<<SCAN_NB, SCAN_B>>>();
    k_scan2<<<1, 1>>>();
    k_scan3<<<SCAN_NB, SCAN_B>>>();
    k_scatter<<<(NE + 255) / 256, 256>>>(ei);

    dim3 g1((NN + 63) / 64, 2);  // FOUT=128
    dim3 g2((NN + 63) / 64, 1);  // FOUT=64
    int aggBlocks = (NN * 32 + 255) / 256;

    // layer 1: x (ext) -> u1 (A) -> h1 (B)
    k_gemm_scale<128, 128, 0, 1><<<g1, 256>>>(x, W1);
    k_agg128<1, 2><<<aggBlocks, 256>>>(b1);
    // layer 2: h1 (B) -> u2 (A) -> h2 (B)
    k_gemm_scale<128, 64, 2, 1><<<g2, 256>>>(nullptr, W2);
    k_agg64<1, 2><<<aggBlocks, 256>>>(b2);
    // layer 3: h2 (B) -> u3 (A) -> h3 (B)
    k_gemm_scale<64, 64, 2, 1><<<g2, 256>>>(nullptr, W3);
    k_agg64<1, 2><<<aggBlocks, 256>>>(b3);

    // head + y copy
    k_head<<<(NN + 127) / 128, 128>>>(prot, Wf0, bf0, Wf1, bf1, y, out, out_size);
}

// round 4
// speedup vs baseline: 1.3476x; 1.3476x over previous
#include <cuda_runtime.h>
#include <cuda_fp16.h>
#include <mma.h>
#include <cstdint>

using namespace nvcuda;

#define NN 50000
#define NE 800000
#define SCAN_B 1024
#define SCAN_NB ((NN + SCAN_B - 1) / SCAN_B)

// ---------------- scratch (static device allocations; no cudaMalloc) ----------------
__device__ int   g_cnt[NN];
__device__ int   g_rowptr[NN + 1];
__device__ int   g_fill[NN];
__device__ int   g_colsrc[NE];
__device__ float g_dinv[NN];
__device__ int   g_bsum[64];
__device__ __align__(16) __half g_u[(size_t)NN * 128];  // pre-agg messages t = A@W (fp16)
__device__ __align__(16) __half g_h[(size_t)NN * 128];  // post-agg activations (fp16)

// ---------------- degree / CSR build ----------------
__global__ void k_zero_cnt() {
    int i = blockIdx.x * blockDim.x + threadIdx.x;
    if (i < NN) g_cnt[i] = 0;
}

__global__ void k_count(const int* __restrict__ ei) {
    int e = blockIdx.x * blockDim.x + threadIdx.x;
    if (e < NE) atomicAdd(&g_cnt[ei[NE + e]], 1);
}

__global__ void k_scan1() {
    __shared__ int s[SCAN_B];
    int t = threadIdx.x;
    int i = blockIdx.x * SCAN_B + t;
    int v = (i < NN) ? g_cnt[i] : 0;
    if (i < NN) g_dinv[i] = rsqrtf((float)(v + 1));  // self loop included in degree
    s[t] = v;
    __syncthreads();
    #pragma unroll
    for (int off = 1; off < SCAN_B; off <<= 1) {
        int add = (t >= off) ? s[t - off] : 0;
        __syncthreads();
        s[t] += add;
        __syncthreads();
    }
    if (i < NN) g_rowptr[i] = s[t] - v;  // exclusive within block
    if (t == SCAN_B - 1) g_bsum[blockIdx.x] = s[t];
}

__global__ void k_scan2() {  // 64 threads, scan 49 block sums
    __shared__ int s[64];
    int t = threadIdx.x;
    int v = (t < SCAN_NB) ? g_bsum[t] : 0;
    s[t] = v;
    __syncthreads();
    #pragma unroll
    for (int off = 1; off < 64; off <<= 1) {
        int add = (t >= off) ? s[t - off] : 0;
        __syncthreads();
        s[t] += add;
        __syncthreads();
    }
    if (t < SCAN_NB) g_bsum[t] = s[t] - v;      // exclusive
    if (t == SCAN_NB - 1) g_rowptr[NN] = s[t];  // total == NE
}

__global__ void k_scan3() {
    int i = blockIdx.x * SCAN_B + threadIdx.x;
    if (i < NN) {
        int r = g_rowptr[i] + g_bsum[blockIdx.x];
        g_rowptr[i] = r;
        g_fill[i] = r;
    }
}

__global__ void k_scatter(const int* __restrict__ ei) {
    int e = blockIdx.x * blockDim.x + threadIdx.x;
    if (e < NE) {
        int s = ei[e];
        int d = ei[NE + e];
        int pos = atomicAdd(&g_fill[d], 1);
        g_colsrc[pos] = s;
    }
}

// ---------------- wmma fp16 GEMM: U[128-tile, FOUT] = A @ W  (fp32 accum, fp16 out) ----------------
// A: layer1 = external fp32 x [NN, FIN]; else g_h fp16. W: [FIN, FOUT] fp32 (row-major, k-major rows).
// Block: 256 threads = 8 warps; warp w computes rows [w*16, w*16+16) x FOUT.
// K streamed through smem in chunks of 32.
template <int FIN, int FOUT, bool AFP32>
__global__ void k_gemm_wmma(const float* __restrict__ Af32, const float* __restrict__ W) {
    __shared__ __align__(16) __half As[128][40];        // 32-wide K chunk + 8 pad
    __shared__ __align__(16) __half Bs[32][FOUT + 8];
    __shared__ __align__(16) float  Cs[8][16][20];      // per-warp epilogue staging

    int tid = threadIdx.x, wid = tid >> 5, lane = tid & 31;
    int row0 = blockIdx.x * 128;

    wmma::fragment<wmma::accumulator, 16, 16, 16, float> acc[FOUT / 16];
    #pragma unroll
    for (int j = 0; j < FOUT / 16; j++) wmma::fill_fragment(acc[j], 0.0f);

    for (int k0 = 0; k0 < FIN; k0 += 32) {
        // A chunk: 128 rows x 32 halves; thread t loads one half-row of 16
        {
            int r = tid >> 1, c0 = (tid & 1) * 16;
            int gr = row0 + r;
            uint4 p0 = make_uint4(0, 0, 0, 0), p1 = make_uint4(0, 0, 0, 0);
            if (gr < NN) {
                if (AFP32) {
                    const float* src = Af32 + (size_t)gr * FIN + k0 + c0;
                    float4 v0 = *(const float4*)(src + 0);
                    float4 v1 = *(const float4*)(src + 4);
                    float4 v2 = *(const float4*)(src + 8);
                    float4 v3 = *(const float4*)(src + 12);
                    __half2 h0 = __floats2half2_rn(v0.x, v0.y), h1 = __floats2half2_rn(v0.z, v0.w);
                    __half2 h2 = __floats2half2_rn(v1.x, v1.y), h3 = __floats2half2_rn(v1.z, v1.w);
                    __half2 h4 = __floats2half2_rn(v2.x, v2.y), h5 = __floats2half2_rn(v2.z, v2.w);
                    __half2 h6 = __floats2half2_rn(v3.x, v3.y), h7 = __floats2half2_rn(v3.z, v3.w);
                    p0 = make_uint4(*(uint32_t*)&h0, *(uint32_t*)&h1, *(uint32_t*)&h2, *(uint32_t*)&h3);
                    p1 = make_uint4(*(uint32_t*)&h4, *(uint32_t*)&h5, *(uint32_t*)&h6, *(uint32_t*)&h7);
                } else {
                    const uint4* src = (const uint4*)(g_h + (size_t)gr * FIN + k0 + c0);
                    p0 = src[0];
                    p1 = src[1];
                }
            }
            *(uint4*)&As[r][c0]     = p0;
            *(uint4*)&As[r][c0 + 8] = p1;
        }
        // B chunk: 32 k-rows x FOUT halves from fp32 W
        for (int i = tid; i < 32 * FOUT / 8; i += 256) {
            int r = i / (FOUT / 8);
            int cb = (i % (FOUT / 8)) * 8;
            const float* src = W + (size_t)(k0 + r) * FOUT + cb;
            float4 v0 = *(const float4*)(src + 0);
            float4 v1 = *(const float4*)(src + 4);
            __half2 h0 = __floats2half2_rn(v0.x, v0.y), h1 = __floats2half2_rn(v0.z, v0.w);
            __half2 h2 = __floats2half2_rn(v1.x, v1.y), h3 = __floats2half2_rn(v1.z, v1.w);
            *(uint4*)&Bs[r][cb] =
                make_uint4(*(uint32_t*)&h0, *(uint32_t*)&h1, *(uint32_t*)&h2, *(uint32_t*)&h3);
        }
        __syncthreads();

        #pragma unroll
        for (int kk = 0; kk < 32; kk += 16) {
            wmma::fragment<wmma::matrix_a, 16, 16, 16, __half, wmma::row_major> af;
            wmma::load_matrix_sync(af, &As[wid * 16][kk], 40);
            #pragma unroll
            for (int j = 0; j < FOUT / 16; j++) {
                wmma::fragment<wmma::matrix_b, 16, 16, 16, __half, wmma::row_major> bf;
                wmma::load_matrix_sync(bf, &Bs[kk][j * 16], FOUT + 8);
                wmma::mma_sync(acc[j], af, bf, acc[j]);
            }
        }
        __syncthreads();
    }

    // epilogue: stage 16x16 fp32 tile in smem, convert to fp16, vector-store to g_u
    #pragma unroll
    for (int j = 0; j < FOUT / 16; j++) {
        wmma::store_matrix_sync(&Cs[wid][0][0], acc[j], 20, wmma::mem_row_major);
        __syncwarp();
        int r = lane >> 1, c0 = (lane & 1) * 8;
        int gr = row0 + wid * 16 + r;
        if (gr < NN) {
            const float* s = &Cs[wid][r][c0];
            __half2 h0 = __floats2half2_rn(s[0], s[1]);
            __half2 h1 = __floats2half2_rn(s[2], s[3]);
            __half2 h2 = __floats2half2_rn(s[4], s[5]);
            __half2 h3 = __floats2half2_rn(s[6], s[7]);
            *(uint4*)(g_u + (size_t)gr * FOUT + j * 16 + c0) =
                make_uint4(*(uint32_t*)&h0, *(uint32_t*)&h1, *(uint32_t*)&h2, *(uint32_t*)&h3);
        }
        __syncwarp();
    }
}

// ---------------- CSR gather aggregation (fp16 in/out, fp32 accum) ----------------
// H[d] = relu(dinv[d] * sum_{s in N(d) U {d}} dinv[s]*U[s] + b)
__device__ __forceinline__ void acc4(float4& a, uint2 v, float d) {
    float2 f0 = __half22float2(*(__half2*)&v.x);
    float2 f1 = __half22float2(*(__half2*)&v.y);
    a.x = fmaf(f0.x, d, a.x); a.y = fmaf(f0.y, d, a.y);
    a.z = fmaf(f1.x, d, a.z); a.w = fmaf(f1.y, d, a.w);
}

__global__ void k_agg128(const float* __restrict__ bias) {
    int w = (blockIdx.x * blockDim.x + threadIdx.x) >> 5;
    int lane = threadIdx.x & 31;
    if (w >= NN) return;
    const uint2* Uv = (const uint2*)g_u;  // 32 uint2 per row (128 halves)
    float dd = g_dinv[w];
    float4 acc = make_float4(0.f, 0.f, 0.f, 0.f);
    acc4(acc, Uv[(size_t)w * 32 + lane], dd);  // self loop
    int e0 = g_rowptr[w], e1 = g_rowptr[w + 1];
    int e = e0;
    for (; e + 4 <= e1; e += 4) {
        int s0 = g_colsrc[e], s1 = g_colsrc[e + 1], s2 = g_colsrc[e + 2], s3 = g_colsrc[e + 3];
        float d0 = g_dinv[s0], d1 = g_dinv[s1], d2 = g_dinv[s2], d3 = g_dinv[s3];
        uint2 v0 = Uv[(size_t)s0 * 32 + lane];
        uint2 v1 = Uv[(size_t)s1 * 32 + lane];
        uint2 v2 = Uv[(size_t)s2 * 32 + lane];
        uint2 v3 = Uv[(size_t)s3 * 32 + lane];
        acc4(acc, v0, d0); acc4(acc, v1, d1); acc4(acc, v2, d2); acc4(acc, v3, d3);
    }
    for (; e < e1; e++) {
        int s = g_colsrc[e];
        acc4(acc, Uv[(size_t)s * 32 + lane], g_dinv[s]);
    }
    float4 bb = ((const float4*)bias)[lane];
    __half2 o0 = __floats2half2_rn(fmaxf(fmaf(acc.x, dd, bb.x), 0.f),
                                   fmaxf(fmaf(acc.y, dd, bb.y), 0.f));
    __half2 o1 = __floats2half2_rn(fmaxf(fmaf(acc.z, dd, bb.z), 0.f),
                                   fmaxf(fmaf(acc.w, dd, bb.w), 0.f));
    ((uint2*)g_h)[(size_t)w * 32 + lane] = make_uint2(*(uint32_t*)&o0, *(uint32_t*)&o1);
}

__global__ void k_agg64(const float* __restrict__ bias) {
    int w = (blockIdx.x * blockDim.x + threadIdx.x) >> 5;
    int lane = threadIdx.x & 31;
    if (w >= NN) return;
    const uint32_t* Uv = (const uint32_t*)g_u;  // 32 half2 per row (64 halves)
    float dd = g_dinv[w];
    float2 acc;
    {
        float2 f = __half22float2(*(__half2*)&Uv[(size_t)w * 32 + lane]);
        acc.x = f.x * dd; acc.y = f.y * dd;
    }
    int e0 = g_rowptr[w], e1 = g_rowptr[w + 1];
    int e = e0;
    for (; e + 4 <= e1; e += 4) {
        int s0 = g_colsrc[e], s1 = g_colsrc[e + 1], s2 = g_colsrc[e + 2], s3 = g_colsrc[e + 3];
        float d0 = g_dinv[s0], d1 = g_dinv[s1], d2 = g_dinv[s2], d3 = g_dinv[s3];
        uint32_t v0 = Uv[(size_t)s0 * 32 + lane];
        uint32_t v1 = Uv[(size_t)s1 * 32 + lane];
        uint32_t v2 = Uv[(size_t)s2 * 32 + lane];
        uint32_t v3 = Uv[(size_t)s3 * 32 + lane];
        float2 f0 = __half22float2(*(__half2*)&v0);
        float2 f1 = __half22float2(*(__half2*)&v1);
        float2 f2 = __half22float2(*(__half2*)&v2);
        float2 f3 = __half22float2(*(__half2*)&v3);
        acc.x = fmaf(f0.x, d0, acc.x); acc.y = fmaf(f0.y, d0, acc.y);
        acc.x = fmaf(f1.x, d1, acc.x); acc.y = fmaf(f1.y, d1, acc.y);
        acc.x = fmaf(f2.x, d2, acc.x); acc.y = fmaf(f2.y, d2, acc.y);
        acc.x = fmaf(f3.x, d3, acc.x); acc.y = fmaf(f3.y, d3, acc.y);
    }
    for (; e < e1; e++) {
        int s = g_colsrc[e];
        float2 f = __half22float2(*(__half2*)&Uv[(size_t)s * 32 + lane]);
        float d = g_dinv[s];
        acc.x = fmaf(f.x, d, acc.x); acc.y = fmaf(f.y, d, acc.y);
    }
    float2 bb = ((const float2*)bias)[lane];
    __half2 o = __floats2half2_rn(fmaxf(fmaf(acc.x, dd, bb.x), 0.f),
                                  fmaxf(fmaf(acc.y, dd, bb.y), 0.f));
    ((uint32_t*)g_h)[(size_t)w * 32 + lane] = *(uint32_t*)&o;
}

// ---------------- prototype-distance head + MLP + y copy ----------------
__device__ __forceinline__ float gelu_exact(float x) {
    return 0.5f * x * (1.0f + erff(x * 0.70710678118654752f));
}

__global__ void k_head(const float* __restrict__ prot,
                       const float* __restrict__ Wf0, const float* __restrict__ bf0,
                       const float* __restrict__ Wf1, const float* __restrict__ bf1,
                       const int* __restrict__ y,
                       float* __restrict__ out, int out_size) {
    __shared__ float hs[128][65];
    __shared__ float ps[16][64];
    __shared__ float pn[16];
    __shared__ float w0[16][8];
    __shared__ float b0[8];
    __shared__ float w1[8];
    __shared__ float b1s;

    int t = threadIdx.x;
    int nd0 = blockIdx.x * 128;

    for (int idx = t; idx < 128 * 64; idx += 128) {
        int r = idx >> 6, c = idx & 63;
        int node = nd0 + r;
        hs[r][c] = (node < NN) ? __half2float(g_h[(size_t)node * 64 + c]) : 0.f;
    }
    for (int idx = t; idx < 16 * 64; idx += 128)
        ps[idx >> 6][idx & 63] = prot[idx];
    if (t < 16 * 8) w0[t >> 3][t & 7] = Wf0[t];
    if (t < 8) { b0[t] = bf0[t]; w1[t] = Wf1[t]; }
    if (t == 0) b1s = bf1[0];
    __syncthreads();
    if (t < 16) {
        float s = 0.f;
        #pragma unroll
        for (int c = 0; c < 64; c++) s += ps[t][c] * ps[t][c];
        pn[t] = s;
    }
    __syncthreads();

    int node = nd0 + t;
    if (node < NN) {
        float hh = 0.f;
        #pragma unroll
        for (int c = 0; c < 64; c++) hh = fmaf(hs[t][c], hs[t][c], hh);

        float sim[16];
        #pragma unroll
        for (int k = 0; k < 16; k++) {
            float dot = 0.f;
            #pragma unroll
            for (int c = 0; c < 64; c++) dot = fmaf(hs[t][c], ps[k][c], dot);
            float d2 = fmaxf(hh + pn[k] - 2.0f * dot, 0.f);
            sim[k] = logf((d2 + 1.0f) / (d2 + 1e-4f));
        }

        float o = b1s;
        #pragma unroll
        for (int j = 0; j < 8; j++) {
            float z = b0[j];
            #pragma unroll
            for (int k = 0; k < 16; k++) z = fmaf(sim[k], w0[k][j], z);
            o = fmaf(gelu_exact(z), w1[j], o);
        }
        out[node] = 1.0f / (1.0f + expf(-o));
        if (NN + node < out_size) out[NN + node] = (float)y[node];
    }
}

// ---------------- launch ----------------
extern "C" void kernel_launch(void* const* d_in, const int* in_sizes, int n_in,
                              void* d_out, int out_size) {
    const float* x    = (const float*)d_in[0];
    const int*   ei   = (const int*)d_in[1];
    const int*   y    = (const int*)d_in[2];
    const float* W1   = (const float*)d_in[3];
    const float* b1   = (const float*)d_in[4];
    const float* W2   = (const float*)d_in[5];
    const float* b2   = (const float*)d_in[6];
    const float* W3   = (const float*)d_in[7];
    const float* b3   = (const float*)d_in[8];
    const float* prot = (const float*)d_in[9];
    const float* Wf0  = (const float*)d_in[10];
    const float* bf0  = (const float*)d_in[11];
    const float* Wf1  = (const float*)d_in[12];
    const float* bf1  = (const float*)d_in[13];
    float* out = (float*)d_out;

    // CSR build
    k_zero_cnt<<<(NN + 255) / 256, 256>>>();
    k_count<<<(NE + 255) / 256, 256>>>(ei);
    k_scan1<<<SCAN_NB, SCAN_B>>>();
    k_scan2<<<1, 64>>>();
    k_scan3<<<SCAN_NB, SCAN_B>>>();
    k_scatter<<<(NE + 255) / 256, 256>>>(ei);

    const int MT = (NN + 127) / 128;  // 391 M-tiles
    int aggBlocks = (NN * 32 + 255) / 256;

    // layer 1: x -> U (fp16) -> h1
    k_gemm_wmma<128, 128, true><<<MT, 256>>>(x, W1);
    k_agg128<<<aggBlocks, 256>>>(b1);
    // layer 2: h1 -> U -> h2
    k_gemm_wmma<128, 64, false><<<MT, 256>>>(nullptr, W2);
    k_agg64<<<aggBlocks, 256>>>(b2);
    // layer 3: h2 -> U -> h3
    k_gemm_wmma<64, 64, false><<<MT, 256>>>(nullptr, W3);
    k_agg64<<<aggBlocks, 256>>>(b3);

    // head + y copy
    k_head<<<(NN + 127) / 128, 128>>>(prot, Wf0, bf0, Wf1, bf1, y, out, out_size);
}